// round 12
// baseline (speedup 1.0000x reference)
#include <cuda_runtime.h>
#include <math.h>

// Problem shape (fixed per reference)
#define NN   100000
#define NE   3200000
#define DIN  128
#define DH   16
#define DOUT 2

// Scratch (static __device__ arrays: allocation-free rule)
static __device__ __align__(16) float g_h1[NN * DH];     // x @ W1          6.4 MB
static __device__ __align__(16) float g_agg1[NN * DH];   // scatter accum   6.4 MB
static __device__ __align__(8)  float g_h2[NN * DOUT];   // relu(...) @ W2  0.8 MB
static __device__ __align__(8)  float g_agg2[NN * DOUT]; // scatter accum   0.8 MB
static __device__ float g_dinv[NN];
static __device__ float g_deg[NN];
static __device__ int   g_is64;   // 1 if edge_index stored as int64, 0 if int32

// ---------------------------------------------------------------------------
// Detect edge_index dtype. Little-endian int64 values < 2^17 have zero high
// words at every odd 32-bit position; genuine int32 indices (uniform 0..N-1)
// essentially never have 32 consecutive zeros there. Deterministic per input.
// ---------------------------------------------------------------------------
__global__ void k_detect(const int* __restrict__ ei32) {
    if (threadIdx.x == 0 && blockIdx.x == 0) {
        int is64 = 1;
        for (int i = 1; i < 64; i += 2)
            if (ei32[i] != 0) { is64 = 0; break; }
        g_is64 = is64;
    }
}

// Uniform-branch index load (only the valid-width path executes).
__device__ __forceinline__ unsigned load_idx(const void* ei, long long pos) {
    if (g_is64) return (unsigned)((const long long*)ei)[pos];
    else        return (unsigned)((const int*)ei)[pos];
}

// ---------------------------------------------------------------------------
// Zero accumulators + degree (graph replays require re-init every launch)
// ---------------------------------------------------------------------------
__global__ void k_zero() {
    int i = blockIdx.x * blockDim.x + threadIdx.x;
    if (i < NN * DH)   g_agg1[i] = 0.f;
    if (i < NN * DOUT) g_agg2[i] = 0.f;
    if (i < NN)        g_deg[i]  = 0.f;
}

// ---------------------------------------------------------------------------
// Degree over dst (real edges only; self-loop handled as +1 in k_dinv)
// ---------------------------------------------------------------------------
__global__ void k_deg(const void* __restrict__ ei) {
    int e = blockIdx.x * blockDim.x + threadIdx.x;
    if (e < NE) {
        unsigned d = load_idx(ei, (long long)NE + e);
        if (d < NN) atomicAdd(&g_deg[d], 1.0f);
    }
}

__global__ void k_dinv() {
    int i = blockIdx.x * blockDim.x + threadIdx.x;
    if (i < NN) g_dinv[i] = rsqrtf(g_deg[i] + 1.0f);  // +1 = self-loop; deg >= 1 always
}

// ---------------------------------------------------------------------------
// GEMM1: h1 = x @ W1   (lane-per-row, W1 broadcast from smem, no reductions)
// ---------------------------------------------------------------------------
__global__ void k_gemm1(const float* __restrict__ x, const float* __restrict__ W1) {
    __shared__ float4 Ws[DIN * DH / 4];  // 8 KB, [k][c/4]
    const float4* w4 = (const float4*)W1;
    for (int i = threadIdx.x; i < DIN * DH / 4; i += blockDim.x) Ws[i] = w4[i];
    __syncthreads();

    int row = blockIdx.x * blockDim.x + threadIdx.x;
    if (row >= NN) return;

    const float4* xr = (const float4*)(x + (size_t)row * DIN);
    float4 a0 = make_float4(0.f, 0.f, 0.f, 0.f);
    float4 a1 = a0, a2 = a0, a3 = a0;

#pragma unroll 8
    for (int k4 = 0; k4 < DIN / 4; k4++) {
        float4 xq = __ldg(xr + k4);
        float xv[4] = {xq.x, xq.y, xq.z, xq.w};
#pragma unroll
        for (int kk = 0; kk < 4; kk++) {
            int k = k4 * 4 + kk;
            float v = xv[kk];
            float4 w0 = Ws[k * 4 + 0], w1 = Ws[k * 4 + 1];
            float4 w2 = Ws[k * 4 + 2], w3 = Ws[k * 4 + 3];
            a0.x += v * w0.x; a0.y += v * w0.y; a0.z += v * w0.z; a0.w += v * w0.w;
            a1.x += v * w1.x; a1.y += v * w1.y; a1.z += v * w1.z; a1.w += v * w1.w;
            a2.x += v * w2.x; a2.y += v * w2.y; a2.z += v * w2.z; a2.w += v * w2.w;
            a3.x += v * w3.x; a3.y += v * w3.y; a3.z += v * w3.z; a3.w += v * w3.w;
        }
    }
    float4* o = (float4*)(g_h1 + (size_t)row * DH);
    o[0] = a0; o[1] = a1; o[2] = a2; o[3] = a3;
}

// ---------------------------------------------------------------------------
// Scatter 1: agg1[dst] += h1[src] * dinv[src] * dinv[dst]   (vector RED to L2)
// ---------------------------------------------------------------------------
__global__ void k_scatter1(const void* __restrict__ ei) {
    int e = blockIdx.x * blockDim.x + threadIdx.x;
    if (e >= NE) return;
    unsigned s = load_idx(ei, e);
    unsigned d = load_idx(ei, (long long)NE + e);
    if (s >= NN || d >= NN) return;
    float nrm = g_dinv[s] * g_dinv[d];
    const float4* hp = (const float4*)(g_h1 + (size_t)s * DH);
    float* ap = g_agg1 + (size_t)d * DH;
#pragma unroll
    for (int q = 0; q < 4; q++) {
        float4 v = __ldg(hp + q);
        asm volatile("red.global.add.v4.f32 [%0], {%1, %2, %3, %4};"
                     :: "l"(ap + 4 * q),
                        "f"(v.x * nrm), "f"(v.y * nrm), "f"(v.z * nrm), "f"(v.w * nrm)
                     : "memory");
    }
}

// ---------------------------------------------------------------------------
// Fused: r = relu(agg1 + h1*dinv^2 + b1);  h2 = r @ W2   (out1 never stored)
// ---------------------------------------------------------------------------
__global__ void k_relu_gemm2(const float* __restrict__ b1, const float* __restrict__ W2) {
    __shared__ float W2s[DH * DOUT];
    __shared__ float b1s[DH];
    if (threadIdx.x < DH * DOUT) W2s[threadIdx.x] = W2[threadIdx.x];
    if (threadIdx.x < DH)        b1s[threadIdx.x] = b1[threadIdx.x];
    __syncthreads();

    int i = blockIdx.x * blockDim.x + threadIdx.x;
    if (i >= NN) return;

    float di  = g_dinv[i];
    float di2 = di * di;
    const float4* ag = (const float4*)(g_agg1 + (size_t)i * DH);
    const float4* hh = (const float4*)(g_h1   + (size_t)i * DH);

    float h2a = 0.f, h2b = 0.f;
#pragma unroll
    for (int q = 0; q < 4; q++) {
        float4 a = ag[q];
        float4 h = hh[q];
        float r;
        r = fmaxf(a.x + h.x * di2 + b1s[q * 4 + 0], 0.f);
        h2a += r * W2s[(q * 4 + 0) * 2 + 0]; h2b += r * W2s[(q * 4 + 0) * 2 + 1];
        r = fmaxf(a.y + h.y * di2 + b1s[q * 4 + 1], 0.f);
        h2a += r * W2s[(q * 4 + 1) * 2 + 0]; h2b += r * W2s[(q * 4 + 1) * 2 + 1];
        r = fmaxf(a.z + h.z * di2 + b1s[q * 4 + 2], 0.f);
        h2a += r * W2s[(q * 4 + 2) * 2 + 0]; h2b += r * W2s[(q * 4 + 2) * 2 + 1];
        r = fmaxf(a.w + h.w * di2 + b1s[q * 4 + 3], 0.f);
        h2a += r * W2s[(q * 4 + 3) * 2 + 0]; h2b += r * W2s[(q * 4 + 3) * 2 + 1];
    }
    *(float2*)(g_h2 + (size_t)i * DOUT) = make_float2(h2a, h2b);
}

// ---------------------------------------------------------------------------
// Scatter 2: agg2[dst] += h2[src] * norm
// ---------------------------------------------------------------------------
__global__ void k_scatter2(const void* __restrict__ ei) {
    int e = blockIdx.x * blockDim.x + threadIdx.x;
    if (e >= NE) return;
    unsigned s = load_idx(ei, e);
    unsigned d = load_idx(ei, (long long)NE + e);
    if (s >= NN || d >= NN) return;
    float nrm = g_dinv[s] * g_dinv[d];
    float2 v = *(const float2*)(g_h2 + (size_t)s * DOUT);
    asm volatile("red.global.add.v2.f32 [%0], {%1, %2};"
                 :: "l"(g_agg2 + (size_t)d * DOUT),
                    "f"(v.x * nrm), "f"(v.y * nrm)
                 : "memory");
}

// ---------------------------------------------------------------------------
// Finalize: z = agg2 + self-loop + b2; log_softmax over 2 classes
// ---------------------------------------------------------------------------
__global__ void k_final(const float* __restrict__ b2, float* __restrict__ out) {
    int i = blockIdx.x * blockDim.x + threadIdx.x;
    if (i >= NN) return;
    float di  = g_dinv[i];
    float di2 = di * di;
    float2 h = *(const float2*)(g_h2   + (size_t)i * DOUT);
    float2 a = *(const float2*)(g_agg2 + (size_t)i * DOUT);
    float z0 = a.x + h.x * di2 + b2[0];
    float z1 = a.y + h.y * di2 + b2[1];
    float m   = fmaxf(z0, z1);
    float lse = m + logf(expf(z0 - m) + expf(z1 - m));
    ((float2*)out)[i] = make_float2(z0 - lse, z1 - lse);
}

// ---------------------------------------------------------------------------
extern "C" void kernel_launch(void* const* d_in, const int* in_sizes, int n_in,
                              void* d_out, int out_size) {
    // Identify inputs by element count (order-independent; all counts unique):
    //   x: 12,800,000   edge_index: 6,400,000   W1: 2048   b1: 16   W2: 32   b2: 2
    const float* x  = nullptr;
    const void*  ei = nullptr;
    const float* W1 = nullptr;
    const float* b1 = nullptr;
    const float* W2 = nullptr;
    const float* b2 = nullptr;
    for (int i = 0; i < n_in; i++) {
        switch (in_sizes[i]) {
            case NN * DIN:   x  = (const float*)d_in[i]; break;
            case 2 * NE:     ei = d_in[i];               break;
            case DIN * DH:   W1 = (const float*)d_in[i]; break;
            case DH:         b1 = (const float*)d_in[i]; break;
            case DH * DOUT:  W2 = (const float*)d_in[i]; break;
            case DOUT:       b2 = (const float*)d_in[i]; break;
            default: break;
        }
    }
    float* out = (float*)d_out;  // [N, 2] float32

    const int thr = 256;
    k_detect    <<<1, 32>>>((const int*)ei);
    k_zero      <<<(NN * DH + thr - 1) / thr, thr>>>();
    k_deg       <<<(NE + thr - 1) / thr, thr>>>(ei);
    k_dinv      <<<(NN + thr - 1) / thr, thr>>>();
    k_gemm1     <<<(NN + thr - 1) / thr, thr>>>(x, W1);
    k_scatter1  <<<(NE + thr - 1) / thr, thr>>>(ei);
    k_relu_gemm2<<<(NN + thr - 1) / thr, thr>>>(b1, W2);
    k_scatter2  <<<(NE + thr - 1) / thr, thr>>>(ei);
    k_final     <<<(NN + thr - 1) / thr, thr>>>(b2, out);
}

// round 13
// speedup vs baseline: 1.4325x; 1.4325x over previous
#include <cuda_runtime.h>
#include <math.h>

// Problem shape (fixed per reference)
#define NN   100000
#define NE   3200000
#define DIN  128
#define DH   16
#define DOUT 2

// Scratch (static __device__ arrays: allocation-free rule)
static __device__ __align__(16) float g_h1[NN * DH];     // (x@W1)*dinv      6.4 MB
static __device__ __align__(16) float g_agg1[NN * DH];   // scatter accum    6.4 MB
static __device__ __align__(8)  float g_h2[NN * DOUT];   // layer-2 msgs     0.8 MB
static __device__ __align__(8)  float g_agg2[NN * DOUT]; // scatter accum    0.8 MB
static __device__ float g_dinv[NN];
static __device__ float g_deg[NN];
static __device__ __align__(8) int2 g_sd[NE];            // packed (src,dst) 25.6 MB
static __device__ int   g_is64;   // 1 if edge_index is int64, 0 if int32

// ---------------------------------------------------------------------------
// Detect edge_index dtype. Little-endian int64 values < 2^17 have zero high
// words at every odd 32-bit position; genuine int32 indices essentially never
// have 32 consecutive zeros there. Deterministic per input.
// ---------------------------------------------------------------------------
__global__ void k_detect(const int* __restrict__ ei32) {
    if (threadIdx.x == 0 && blockIdx.x == 0) {
        int is64 = 1;
        for (int i = 1; i < 64; i += 2)
            if (ei32[i] != 0) { is64 = 0; break; }
        g_is64 = is64;
    }
}

// ---------------------------------------------------------------------------
// Zero accumulators + degree (graph replays require re-init every launch)
// ---------------------------------------------------------------------------
__global__ void k_zero() {
    int i = blockIdx.x * blockDim.x + threadIdx.x;
    if (i < NN * DH)   g_agg1[i] = 0.f;
    if (i < NN * DOUT) g_agg2[i] = 0.f;
    if (i < NN)        g_deg[i]  = 0.f;
}

// ---------------------------------------------------------------------------
// Prep: decode indices once -> packed int2, and accumulate dst degree.
// ---------------------------------------------------------------------------
__global__ void k_prep(const void* __restrict__ ei) {
    int e = blockIdx.x * blockDim.x + threadIdx.x;
    if (e >= NE) return;
    int s, d;
    if (g_is64) {
        s = (int)((const long long*)ei)[e];
        d = (int)((const long long*)ei)[(long long)NE + e];
    } else {
        s = ((const int*)ei)[e];
        d = ((const int*)ei)[NE + e];
    }
    g_sd[e] = make_int2(s, d);
    if ((unsigned)d < NN) atomicAdd(&g_deg[d], 1.0f);
}

__global__ void k_dinv() {
    int i = blockIdx.x * blockDim.x + threadIdx.x;
    if (i < NN) g_dinv[i] = rsqrtf(g_deg[i] + 1.0f);  // +1 = self-loop
}

// ---------------------------------------------------------------------------
// GEMM1: h1' = (x @ W1) * dinv[row]   (lane-per-row, W1 broadcast from smem)
// Pre-scaling by dinv[src] makes the edge normalization separable:
//   norm*h1[s] = dinv[d] * (dinv[s]*h1[s]) = dinv[d] * h1'[s]
// ---------------------------------------------------------------------------
__global__ void k_gemm1(const float* __restrict__ x, const float* __restrict__ W1) {
    __shared__ float4 Ws[DIN * DH / 4];  // 8 KB, [k][c/4]
    const float4* w4 = (const float4*)W1;
    for (int i = threadIdx.x; i < DIN * DH / 4; i += blockDim.x) Ws[i] = w4[i];
    __syncthreads();

    int row = blockIdx.x * blockDim.x + threadIdx.x;
    if (row >= NN) return;

    const float4* xr = (const float4*)(x + (size_t)row * DIN);
    float4 a0 = make_float4(0.f, 0.f, 0.f, 0.f);
    float4 a1 = a0, a2 = a0, a3 = a0;

#pragma unroll 8
    for (int k4 = 0; k4 < DIN / 4; k4++) {
        float4 xq = __ldg(xr + k4);
        float xv[4] = {xq.x, xq.y, xq.z, xq.w};
#pragma unroll
        for (int kk = 0; kk < 4; kk++) {
            int k = k4 * 4 + kk;
            float v = xv[kk];
            float4 w0 = Ws[k * 4 + 0], w1 = Ws[k * 4 + 1];
            float4 w2 = Ws[k * 4 + 2], w3 = Ws[k * 4 + 3];
            a0.x += v * w0.x; a0.y += v * w0.y; a0.z += v * w0.z; a0.w += v * w0.w;
            a1.x += v * w1.x; a1.y += v * w1.y; a1.z += v * w1.z; a1.w += v * w1.w;
            a2.x += v * w2.x; a2.y += v * w2.y; a2.z += v * w2.z; a2.w += v * w2.w;
            a3.x += v * w3.x; a3.y += v * w3.y; a3.z += v * w3.z; a3.w += v * w3.w;
        }
    }
    float di = g_dinv[row];
    a0.x *= di; a0.y *= di; a0.z *= di; a0.w *= di;
    a1.x *= di; a1.y *= di; a1.z *= di; a1.w *= di;
    a2.x *= di; a2.y *= di; a2.z *= di; a2.w *= di;
    a3.x *= di; a3.y *= di; a3.z *= di; a3.w *= di;
    float4* o = (float4*)(g_h1 + (size_t)row * DH);
    o[0] = a0; o[1] = a1; o[2] = a2; o[3] = a3;
}

// ---------------------------------------------------------------------------
// Scatter 1 (quad-per-edge): agg1[dst] += h1'[src]  (unnormalized; dinv[dst]
// applied later). 4 consecutive lanes cover one edge's 64B payload, so each
// warp gather/RED touches 8 contiguous 64B rows instead of 32 scattered lines.
// ---------------------------------------------------------------------------
__global__ void k_scatter1(int dummy) {
    int gid = blockIdx.x * blockDim.x + threadIdx.x;
    int e = gid >> 2;
    int q = gid & 3;
    if (e >= NE) return;
    int2 sd = __ldg(&g_sd[e]);
    if ((unsigned)sd.x >= NN || (unsigned)sd.y >= NN) return;
    float4 v = __ldg((const float4*)(g_h1 + (size_t)sd.x * DH) + q);
    float* ap = g_agg1 + (size_t)sd.y * DH + 4 * q;
    asm volatile("red.global.add.v4.f32 [%0], {%1, %2, %3, %4};"
                 :: "l"(ap), "f"(v.x), "f"(v.y), "f"(v.z), "f"(v.w)
                 : "memory");
}

// ---------------------------------------------------------------------------
// Fused: r = relu(dinv*(agg1 + h1') + b1);  h2' = (r @ W2) * dinv
//   dinv*agg1      = sum over in-edges of norm*h1[s]
//   dinv*h1'       = dinv^2*h1[i] = self-loop term
//   h2 pre-scaled by dinv for the layer-2 separable scatter.
// ---------------------------------------------------------------------------
__global__ void k_relu_gemm2(const float* __restrict__ b1, const float* __restrict__ W2) {
    __shared__ float W2s[DH * DOUT];
    __shared__ float b1s[DH];
    if (threadIdx.x < DH * DOUT) W2s[threadIdx.x] = W2[threadIdx.x];
    if (threadIdx.x < DH)        b1s[threadIdx.x] = b1[threadIdx.x];
    __syncthreads();

    int i = blockIdx.x * blockDim.x + threadIdx.x;
    if (i >= NN) return;

    float di = g_dinv[i];
    const float4* ag = (const float4*)(g_agg1 + (size_t)i * DH);
    const float4* hh = (const float4*)(g_h1   + (size_t)i * DH);

    float h2a = 0.f, h2b = 0.f;
#pragma unroll
    for (int q = 0; q < 4; q++) {
        float4 a = ag[q];
        float4 h = hh[q];
        float r;
        r = fmaxf(di * (a.x + h.x) + b1s[q * 4 + 0], 0.f);
        h2a += r * W2s[(q * 4 + 0) * 2 + 0]; h2b += r * W2s[(q * 4 + 0) * 2 + 1];
        r = fmaxf(di * (a.y + h.y) + b1s[q * 4 + 1], 0.f);
        h2a += r * W2s[(q * 4 + 1) * 2 + 0]; h2b += r * W2s[(q * 4 + 1) * 2 + 1];
        r = fmaxf(di * (a.z + h.z) + b1s[q * 4 + 2], 0.f);
        h2a += r * W2s[(q * 4 + 2) * 2 + 0]; h2b += r * W2s[(q * 4 + 2) * 2 + 1];
        r = fmaxf(di * (a.w + h.w) + b1s[q * 4 + 3], 0.f);
        h2a += r * W2s[(q * 4 + 3) * 2 + 0]; h2b += r * W2s[(q * 4 + 3) * 2 + 1];
    }
    *(float2*)(g_h2 + (size_t)i * DOUT) = make_float2(h2a * di, h2b * di);
}

// ---------------------------------------------------------------------------
// Scatter 2: agg2[dst] += h2'[src]   (8B payload, lane-per-edge)
// ---------------------------------------------------------------------------
__global__ void k_scatter2(int dummy) {
    int e = blockIdx.x * blockDim.x + threadIdx.x;
    if (e >= NE) return;
    int2 sd = __ldg(&g_sd[e]);
    if ((unsigned)sd.x >= NN || (unsigned)sd.y >= NN) return;
    float2 v = __ldg((const float2*)(g_h2 + (size_t)sd.x * DOUT));
    asm volatile("red.global.add.v2.f32 [%0], {%1, %2};"
                 :: "l"(g_agg2 + (size_t)sd.y * DOUT), "f"(v.x), "f"(v.y)
                 : "memory");
}

// ---------------------------------------------------------------------------
// Finalize: z = dinv*(agg2 + h2') + b2; log_softmax over 2 classes
// ---------------------------------------------------------------------------
__global__ void k_final(const float* __restrict__ b2, float* __restrict__ out) {
    int i = blockIdx.x * blockDim.x + threadIdx.x;
    if (i >= NN) return;
    float di = g_dinv[i];
    float2 h = *(const float2*)(g_h2   + (size_t)i * DOUT);
    float2 a = *(const float2*)(g_agg2 + (size_t)i * DOUT);
    float z0 = di * (a.x + h.x) + b2[0];
    float z1 = di * (a.y + h.y) + b2[1];
    float m   = fmaxf(z0, z1);
    float lse = m + logf(expf(z0 - m) + expf(z1 - m));
    ((float2*)out)[i] = make_float2(z0 - lse, z1 - lse);
}

// ---------------------------------------------------------------------------
extern "C" void kernel_launch(void* const* d_in, const int* in_sizes, int n_in,
                              void* d_out, int out_size) {
    // Identify inputs by element count (order-independent; all counts unique):
    //   x: 12,800,000   edge_index: 6,400,000   W1: 2048   b1: 16   W2: 32   b2: 2
    const float* x  = nullptr;
    const void*  ei = nullptr;
    const float* W1 = nullptr;
    const float* b1 = nullptr;
    const float* W2 = nullptr;
    const float* b2 = nullptr;
    for (int i = 0; i < n_in; i++) {
        switch (in_sizes[i]) {
            case NN * DIN:   x  = (const float*)d_in[i]; break;
            case 2 * NE:     ei = d_in[i];               break;
            case DIN * DH:   W1 = (const float*)d_in[i]; break;
            case DH:         b1 = (const float*)d_in[i]; break;
            case DH * DOUT:  W2 = (const float*)d_in[i]; break;
            case DOUT:       b2 = (const float*)d_in[i]; break;
            default: break;
        }
    }
    float* out = (float*)d_out;  // [N, 2] float32

    const int thr = 256;
    k_detect    <<<1, 32>>>((const int*)ei);
    k_zero      <<<(NN * DH + thr - 1) / thr, thr>>>();
    k_prep      <<<(NE + thr - 1) / thr, thr>>>(ei);
    k_dinv      <<<(NN + thr - 1) / thr, thr>>>();
    k_gemm1     <<<(NN + thr - 1) / thr, thr>>>(x, W1);
    k_scatter1  <<<(NE * 4 + thr - 1) / thr, thr>>>(0);
    k_relu_gemm2<<<(NN + thr - 1) / thr, thr>>>(b1, W2);
    k_scatter2  <<<(NE + thr - 1) / thr, thr>>>(0);
    k_final     <<<(NN + thr - 1) / thr, thr>>>(b2, out);
}